// round 7
// baseline (speedup 1.0000x reference)
#include <cuda_runtime.h>
#include <cuda_bf16.h>
#include <cstdint>

#define NN 10000
#define EE 160000
#define FF 512
#define BM 128
#define BN 64
#define BK 16
#define NT 32               // 512/16 k-tiles
// smem stage layout (bytes): Ahi 4096 | Alo 4096 | Bhi 2048 | Blo 2048
#define STG_B 12288

// ---------------- scratch (__device__ globals; no allocs) ----------------
__device__ __align__(16) float g_B[NN * FF];
__device__ __align__(16) __nv_bfloat16 g_Xhi[NN * FF];
__device__ __align__(16) __nv_bfloat16 g_Xlo[NN * FF];
__device__ __align__(16) __nv_bfloat16 g_Wthi[FF * FF];   // transposed: [n][k]
__device__ __align__(16) __nv_bfloat16 g_Wtlo[FF * FF];
__device__ float g_dis[NN];
__device__ int   g_deg[NN];
__device__ int   g_rowptr[NN + 1];
__device__ int   g_cur[NN];
__device__ int   g_srcidx[EE];
__device__ float g_ew[EE];
__device__ int   g_is64;

__device__ __forceinline__ uint32_t stu32(const void* p) {
    uint32_t a;
    asm("{ .reg .u64 t; cvta.to.shared.u64 t, %1; cvt.u32.u64 %0, t; }" : "=r"(a) : "l"(p));
    return a;
}

// swizzled byte offset of (row r, 16B-chunk c) in a [rows x 16] bf16 tile
__device__ __forceinline__ uint32_t tswz(int r, int c) {
    return (uint32_t)((r * 32 + c * 16) ^ (((r >> 2) & 7) << 4));
}

// ---------------- detect edge dtype + zero degree (fused) ----------------
__global__ void __launch_bounds__(256) k_detect(const int* __restrict__ ei32) {
    if (blockIdx.x < 40) {
        int i = blockIdx.x * 256 + threadIdx.x;
        if (i < NN) g_deg[i] = 0;
        return;
    }
    __shared__ int red[256];
    int t = threadIdx.x;
    int acc = 0;
    for (int w = 1 + 2 * t; w < 4096; w += 512) acc |= ei32[w];
    red[t] = acc;
    __syncthreads();
    for (int off = 128; off > 0; off >>= 1) {
        if (t < off) red[t] |= red[t + off];
        __syncthreads();
    }
    if (t == 0) g_is64 = (red[0] == 0) ? 1 : 0;
}

__device__ __forceinline__ int edge_at(const void* ei, int idx) {
    if (g_is64) return (int)((const long long*)ei)[idx];
    return ((const int*)ei)[idx];
}

// ---------------- degree accumulate ----------------
__global__ void k_deg_acc(const void* __restrict__ ei) {
    int e = blockIdx.x * 256 + threadIdx.x;
    if (e >= EE) return;
    int c = edge_at(ei, EE + e);
    if ((unsigned)c < NN) atomicAdd(&g_deg[c], 1);
}

// ---------------- scan (shuffle-based) + dis computation (fused) ----------------
__global__ void __launch_bounds__(1024) k_scan() {
    __shared__ int wsum[32];
    __shared__ int carry_s;
    const int t = threadIdx.x, lane = t & 31, w = t >> 5;
    if (t == 0) carry_s = 0;
    __syncthreads();
    for (int base = 0; base < NN; base += 1024) {
        int i = base + t;
        int v = (i < NN) ? g_deg[i] : 0;
        // inclusive warp scan
        int s = v;
#pragma unroll
        for (int o = 1; o < 32; o <<= 1) {
            int x = __shfl_up_sync(0xFFFFFFFFu, s, o);
            if (lane >= o) s += x;
        }
        if (lane == 31) wsum[w] = s;
        __syncthreads();
        if (w == 0) {
            int ws = wsum[lane];
#pragma unroll
            for (int o = 1; o < 32; o <<= 1) {
                int x = __shfl_up_sync(0xFFFFFFFFu, ws, o);
                if (lane >= o) ws += x;
            }
            wsum[lane] = ws;
        }
        __syncthreads();
        int excl = carry_s + (w > 0 ? wsum[w - 1] : 0) + s - v;
        if (i < NN) {
            g_rowptr[i] = excl;
            g_cur[i] = excl;
            g_dis[i] = rsqrtf(1.0f + (float)v);
        }
        __syncthreads();
        if (t == 0) carry_s += wsum[31];
        __syncthreads();
    }
    if (t == 0) g_rowptr[NN] = carry_s;
}

// ---------------- CSR fill ----------------
__global__ void k_fill(const void* __restrict__ ei) {
    int e = blockIdx.x * 256 + threadIdx.x;
    if (e >= EE) return;
    int r = edge_at(ei, e);
    int c = edge_at(ei, EE + e);
    if ((unsigned)r >= NN || (unsigned)c >= NN) return;
    int pos = atomicAdd(&g_cur[c], 1);
    if ((unsigned)pos < EE) {
        g_srcidx[pos] = r;
        g_ew[pos] = g_dis[r] * g_dis[c];
    }
}

// ---------------- fp32 -> bf16 hi/lo split of the input x (layer 1 only) ----------------
__global__ void __launch_bounds__(256) k_cvt_x(const float* __restrict__ src) {
    int idx = blockIdx.x * 256 + threadIdx.x;
    if (idx >= NN * FF / 4) return;
    float4 v = ((const float4*)src)[idx];
    __nv_bfloat16 h0 = __float2bfloat16(v.x), h1 = __float2bfloat16(v.y);
    __nv_bfloat16 h2 = __float2bfloat16(v.z), h3 = __float2bfloat16(v.w);
    __nv_bfloat16 l0 = __float2bfloat16(v.x - __bfloat162float(h0));
    __nv_bfloat16 l1 = __float2bfloat16(v.y - __bfloat162float(h1));
    __nv_bfloat16 l2 = __float2bfloat16(v.z - __bfloat162float(h2));
    __nv_bfloat16 l3 = __float2bfloat16(v.w - __bfloat162float(h3));
    __nv_bfloat162* ph = (__nv_bfloat162*)(g_Xhi + (size_t)idx * 4);
    __nv_bfloat162* pl = (__nv_bfloat162*)(g_Xlo + (size_t)idx * 4);
    ph[0] = __nv_bfloat162(h0, h1); ph[1] = __nv_bfloat162(h2, h3);
    pl[0] = __nv_bfloat162(l0, l1); pl[1] = __nv_bfloat162(l2, l3);
}

// ---------------- weight transpose + hi/lo split: Wt[n][k] = W[k][n] ----------------
__global__ void __launch_bounds__(256) k_cvt_w(const float* __restrict__ W) {
    __shared__ float tile[32][33];
    int tx = threadIdx.x & 31, ty = threadIdx.x >> 5;
    int bn = blockIdx.x * 32, bk = blockIdx.y * 32;
    for (int r = ty; r < 32; r += 8)
        tile[r][tx] = W[(size_t)(bk + r) * FF + bn + tx];
    __syncthreads();
    for (int r = ty; r < 32; r += 8) {
        float v = tile[tx][r];
        __nv_bfloat16 h = __float2bfloat16(v);
        g_Wthi[(size_t)(bn + r) * FF + bk + tx] = h;
        g_Wtlo[(size_t)(bn + r) * FF + bk + tx] = __float2bfloat16(v - __bfloat162float(h));
    }
}

// ---------------- fused split-bf16 GEMM: g_B = Xhi*Whi + Xhi*Wlo + Xlo*Whi ----------------
// BM=128, BN=64, 128 threads, 2 CTAs/SM for cross-CTA load/MMA overlap.
__global__ void __launch_bounds__(128, 2) k_gemm_mma() {
    __shared__ __align__(16) unsigned char sm[2][STG_B];

    const int tid = threadIdx.x;
    const int lane = tid & 31, wid = tid >> 5;
    const int n0 = blockIdx.x * BN, m0 = blockIdx.y * BM;
    const int mbase = (wid >> 1) * 64, nbase = (wid & 1) * 32;
    const uint32_t smb = stu32(sm);

    float d[4][4][4];
#pragma unroll
    for (int i = 0; i < 4; i++)
#pragma unroll
        for (int j = 0; j < 4; j++)
#pragma unroll
            for (int q = 0; q < 4; q++) d[i][j][q] = 0.0f;

    const int brow = tid >> 1, bch = tid & 1;   // B loader mapping
    auto load_tiles = [&](int it, int buf) {
        const int kb = it * BK;
        const uint32_t base = smb + buf * STG_B;
        // A: 128 rows x 2 chunks (hi at +0, lo at +4096); thread t does row=t, ch=0,1
        const size_t xrow = (size_t)(m0 + tid) * FF + kb;
        int szx = (m0 + tid) < NN ? 16 : 0;
#pragma unroll
        for (int ch = 0; ch < 2; ch++) {
            uint32_t o = tswz(tid, ch);
            asm volatile("cp.async.cg.shared.global [%0], [%1], 16, %2;"
                         :: "r"(base + o), "l"((const void*)(g_Xhi + xrow + ch * 8)), "r"(szx));
            asm volatile("cp.async.cg.shared.global [%0], [%1], 16, %2;"
                         :: "r"(base + 4096 + o), "l"((const void*)(g_Xlo + xrow + ch * 8)), "r"(szx));
        }
        // B: 64 rows x 2 chunks (hi at +8192, lo at +10240); thread t does row=t>>1, ch=t&1
        const size_t wrow = (size_t)(n0 + brow) * FF + kb + bch * 8;
        uint32_t ob = tswz(brow, bch);
        asm volatile("cp.async.cg.shared.global [%0], [%1], 16;"
                     :: "r"(base + 8192 + ob), "l"((const void*)(g_Wthi + wrow)));
        asm volatile("cp.async.cg.shared.global [%0], [%1], 16;"
                     :: "r"(base + 10240 + ob), "l"((const void*)(g_Wtlo + wrow)));
        asm volatile("cp.async.commit_group;" ::: "memory");
    };

    load_tiles(0, 0);

    const int frow = lane & 15, fch = lane >> 4;
    for (int it = 0; it < NT; it++) {
        const int buf = it & 1;
        if (it + 1 < NT) {
            load_tiles(it + 1, buf ^ 1);
            asm volatile("cp.async.wait_group 1;" ::: "memory");
        } else {
            asm volatile("cp.async.wait_group 0;" ::: "memory");
        }
        __syncthreads();

        const uint32_t base = smb + buf * STG_B;
        uint32_t aHi[4][4], aLo[4][4], bHi[4][2], bLo[4][2];
#pragma unroll
        for (int mf = 0; mf < 4; mf++) {
            uint32_t off = tswz(mbase + mf * 16 + frow, fch);
            asm volatile("ldmatrix.sync.aligned.m8n8.x4.shared.b16 {%0,%1,%2,%3}, [%4];"
                         : "=r"(aHi[mf][0]), "=r"(aHi[mf][1]), "=r"(aHi[mf][2]), "=r"(aHi[mf][3])
                         : "r"(base + off));
            asm volatile("ldmatrix.sync.aligned.m8n8.x4.shared.b16 {%0,%1,%2,%3}, [%4];"
                         : "=r"(aLo[mf][0]), "=r"(aLo[mf][1]), "=r"(aLo[mf][2]), "=r"(aLo[mf][3])
                         : "r"(base + 4096 + off));
        }
#pragma unroll
        for (int nb = 0; nb < 2; nb++) {
            uint32_t off = tswz(nbase + nb * 16 + frow, fch);
            uint32_t r0, r1, r2, r3;
            asm volatile("ldmatrix.sync.aligned.m8n8.x4.shared.b16 {%0,%1,%2,%3}, [%4];"
                         : "=r"(r0), "=r"(r1), "=r"(r2), "=r"(r3)
                         : "r"(base + 8192 + off));
            bHi[nb * 2][0] = r0; bHi[nb * 2][1] = r2;
            bHi[nb * 2 + 1][0] = r1; bHi[nb * 2 + 1][1] = r3;
            asm volatile("ldmatrix.sync.aligned.m8n8.x4.shared.b16 {%0,%1,%2,%3}, [%4];"
                         : "=r"(r0), "=r"(r1), "=r"(r2), "=r"(r3)
                         : "r"(base + 10240 + off));
            bLo[nb * 2][0] = r0; bLo[nb * 2][1] = r2;
            bLo[nb * 2 + 1][0] = r1; bLo[nb * 2 + 1][1] = r3;
        }

#define MMA(A, B, mf, nf)                                                         \
        asm volatile(                                                             \
            "mma.sync.aligned.m16n8k16.row.col.f32.bf16.bf16.f32 "                \
            "{%0,%1,%2,%3}, {%4,%5,%6,%7}, {%8,%9}, {%0,%1,%2,%3};"               \
            : "+f"(d[mf][nf][0]), "+f"(d[mf][nf][1]),                             \
              "+f"(d[mf][nf][2]), "+f"(d[mf][nf][3])                              \
            : "r"(A[mf][0]), "r"(A[mf][1]), "r"(A[mf][2]), "r"(A[mf][3]),         \
              "r"(B[nf][0]), "r"(B[nf][1]))
#pragma unroll
        for (int mf = 0; mf < 4; mf++)
#pragma unroll
            for (int nf = 0; nf < 4; nf++) {
                MMA(aHi, bHi, mf, nf);
                MMA(aHi, bLo, mf, nf);
                MMA(aLo, bHi, mf, nf);
            }
#undef MMA
        __syncthreads();
    }

    // epilogue: write fp32 result to g_B
    const int g = lane >> 2, tg = lane & 3;
#pragma unroll
    for (int mf = 0; mf < 4; mf++) {
        int row0 = m0 + mbase + mf * 16 + g;
        int row1 = row0 + 8;
#pragma unroll
        for (int nf = 0; nf < 4; nf++) {
            int col = n0 + nbase + nf * 8 + tg * 2;
            if (row0 < NN)
                *(float2*)(g_B + (size_t)row0 * FF + col) = make_float2(d[mf][nf][0], d[mf][nf][1]);
            if (row1 < NN)
                *(float2*)(g_B + (size_t)row1 * FF + col) = make_float2(d[mf][nf][2], d[mf][nf][3]);
        }
    }
}

// ---------------- fused aggregation (reads g_B; writes hi/lo or fp32) ----------------
__global__ void __launch_bounds__(128) k_agg(const float* __restrict__ bias,
                                             int mode, float* __restrict__ extOut) {
    const float* h = g_B;
    __shared__ int   sh_src[128];
    __shared__ float sh_w[128];
    const int i = blockIdx.x;
    const int t = threadIdx.x;

    float dd = g_dis[i];
    float w0 = dd * dd;
    float4 acc = ((const float4*)(h + (size_t)i * FF))[t];
    acc.x *= w0; acc.y *= w0; acc.z *= w0; acc.w *= w0;

    const int s = g_rowptr[i], e2 = g_rowptr[i + 1];
    for (int base = s; base < e2; base += 128) {
        int m = e2 - base;
        if (m > 128) m = 128;
        if (t < m) {
            sh_src[t] = g_srcidx[base + t];
            sh_w[t]   = g_ew[base + t];
        }
        __syncthreads();
#pragma unroll 4
        for (int j = 0; j < m; j++) {
            const float4 v = ((const float4*)(h + (size_t)sh_src[j] * FF))[t];
            const float w = sh_w[j];
            acc.x += v.x * w; acc.y += v.y * w;
            acc.z += v.z * w; acc.w += v.w * w;
        }
        __syncthreads();
    }

    float4 bb = ((const float4*)bias)[t];
    acc.x += bb.x; acc.y += bb.y; acc.z += bb.z; acc.w += bb.w;

    if (mode) {
        acc.x = fmaxf(acc.x, 0.f); acc.y = fmaxf(acc.y, 0.f);
        acc.z = fmaxf(acc.z, 0.f); acc.w = fmaxf(acc.w, 0.f);
        __nv_bfloat16 h0 = __float2bfloat16(acc.x), h1 = __float2bfloat16(acc.y);
        __nv_bfloat16 h2 = __float2bfloat16(acc.z), h3 = __float2bfloat16(acc.w);
        __nv_bfloat16 l0 = __float2bfloat16(acc.x - __bfloat162float(h0));
        __nv_bfloat16 l1 = __float2bfloat16(acc.y - __bfloat162float(h1));
        __nv_bfloat16 l2 = __float2bfloat16(acc.z - __bfloat162float(h2));
        __nv_bfloat16 l3 = __float2bfloat16(acc.w - __bfloat162float(h3));
        size_t o = (size_t)i * FF + t * 4;
        __nv_bfloat162* ph = (__nv_bfloat162*)(g_Xhi + o);
        __nv_bfloat162* pl = (__nv_bfloat162*)(g_Xlo + o);
        ph[0] = __nv_bfloat162(h0, h1); ph[1] = __nv_bfloat162(h2, h3);
        pl[0] = __nv_bfloat162(l0, l1); pl[1] = __nv_bfloat162(l2, l3);
    } else {
        ((float4*)(extOut + (size_t)i * FF))[t] = acc;
    }
}

// ---------------- launcher (kernel launches ONLY) ----------------
extern "C" void kernel_launch(void* const* d_in, const int* in_sizes, int n_in,
                              void* d_out, int out_size) {
    const float* x   = (const float*)d_in[0];
    const void*  ei  = d_in[1];
    const float* W1  = (const float*)d_in[2];
    const float* b1  = (const float*)d_in[3];
    const float* W2  = (const float*)d_in[4];
    const float* b2  = (const float*)d_in[5];
    const float* W3  = (const float*)d_in[6];
    const float* b3  = (const float*)d_in[7];
    float* out       = (float*)d_out;

    dim3 gemm_grid(FF / BN, (NN + BM - 1) / BM);   // (8, 79)
    dim3 cvtw_grid(16, 16);
    int cvtx_blocks = (NN * FF / 4 + 255) / 256;

    // setup: detect dtype + zero deg (fused) -> degree -> scan+dis -> fill
    k_detect<<<41, 256>>>((const int*)ei);
    k_deg_acc<<<(EE + 255) / 256, 256>>>(ei);
    k_scan<<<1, 1024>>>();
    k_fill<<<(EE + 255) / 256, 256>>>(ei);

    // Layer 1
    k_cvt_w<<<cvtw_grid, 256>>>(W1);
    k_cvt_x<<<cvtx_blocks, 256>>>(x);
    k_gemm_mma<<<gemm_grid, 128>>>();
    k_agg<<<NN, 128>>>(b1, 1, nullptr);
    // Layer 2
    k_cvt_w<<<cvtw_grid, 256>>>(W2);
    k_gemm_mma<<<gemm_grid, 128>>>();
    k_agg<<<NN, 128>>>(b2, 1, nullptr);
    // Layer 3 (final, fp32 out, no relu)
    k_cvt_w<<<cvtw_grid, 256>>>(W3);
    k_gemm_mma<<<gemm_grid, 128>>>();
    k_agg<<<NN, 128>>>(b3, 0, out);
}

// round 8
// speedup vs baseline: 1.1017x; 1.1017x over previous
#include <cuda_runtime.h>
#include <cuda_bf16.h>
#include <cstdint>

#define NN 10000
#define EE 160000
#define FF 512
#define BM 128
#define BN 128
#define BK 16
#define NT 32               // 512/16 k-tiles
#define TILE_B 4096         // bytes per smem tile (128 rows x 32B)
#define NSTG 3              // cp.async pipeline stages

// ---------------- scratch (__device__ globals; no allocs) ----------------
__device__ __align__(16) float g_B[NN * FF];
__device__ __align__(16) __nv_bfloat16 g_Xhi[NN * FF];
__device__ __align__(16) __nv_bfloat16 g_Xlo[NN * FF];
__device__ __align__(16) __nv_bfloat16 g_Wthi[FF * FF];   // transposed: [n][k]
__device__ __align__(16) __nv_bfloat16 g_Wtlo[FF * FF];
__device__ float g_dis[NN];
__device__ int   g_deg[NN];
__device__ int   g_rowptr[NN + 1];
__device__ int   g_cur[NN];
__device__ int   g_srcidx[EE];
__device__ float g_ew[EE];
__device__ int   g_is64;

__device__ __forceinline__ uint32_t stu32(const void* p) {
    uint32_t a;
    asm("{ .reg .u64 t; cvta.to.shared.u64 t, %1; cvt.u32.u64 %0, t; }" : "=r"(a) : "l"(p));
    return a;
}

// swizzled byte offset of (row r, 16B-chunk c) in a [rows x 16] bf16 tile
__device__ __forceinline__ uint32_t tswz(int r, int c) {
    return (uint32_t)((r * 32 + c * 16) ^ (((r >> 2) & 7) << 4));
}

// ---------------- detect edge dtype + zero degree (fused) ----------------
__global__ void __launch_bounds__(256) k_detect(const int* __restrict__ ei32) {
    if (blockIdx.x < 40) {
        int i = blockIdx.x * 256 + threadIdx.x;
        if (i < NN) g_deg[i] = 0;
        return;
    }
    __shared__ int red[256];
    int t = threadIdx.x;
    int acc = 0;
    for (int w = 1 + 2 * t; w < 4096; w += 512) acc |= ei32[w];
    red[t] = acc;
    __syncthreads();
    for (int off = 128; off > 0; off >>= 1) {
        if (t < off) red[t] |= red[t + off];
        __syncthreads();
    }
    if (t == 0) g_is64 = (red[0] == 0) ? 1 : 0;
}

__device__ __forceinline__ int edge_at(const void* ei, int idx) {
    if (g_is64) return (int)((const long long*)ei)[idx];
    return ((const int*)ei)[idx];
}

// ---------------- degree accumulate ----------------
__global__ void k_deg_acc(const void* __restrict__ ei) {
    int e = blockIdx.x * 256 + threadIdx.x;
    if (e >= EE) return;
    int c = edge_at(ei, EE + e);
    if ((unsigned)c < NN) atomicAdd(&g_deg[c], 1);
}

// ---------------- scan (shuffle-based) + dis computation (fused) ----------------
__global__ void __launch_bounds__(1024) k_scan() {
    __shared__ int wsum[32];
    __shared__ int carry_s;
    const int t = threadIdx.x, lane = t & 31, w = t >> 5;
    if (t == 0) carry_s = 0;
    __syncthreads();
    for (int base = 0; base < NN; base += 1024) {
        int i = base + t;
        int v = (i < NN) ? g_deg[i] : 0;
        int s = v;
#pragma unroll
        for (int o = 1; o < 32; o <<= 1) {
            int x = __shfl_up_sync(0xFFFFFFFFu, s, o);
            if (lane >= o) s += x;
        }
        if (lane == 31) wsum[w] = s;
        __syncthreads();
        if (w == 0) {
            int ws = wsum[lane];
#pragma unroll
            for (int o = 1; o < 32; o <<= 1) {
                int x = __shfl_up_sync(0xFFFFFFFFu, ws, o);
                if (lane >= o) ws += x;
            }
            wsum[lane] = ws;
        }
        __syncthreads();
        int excl = carry_s + (w > 0 ? wsum[w - 1] : 0) + s - v;
        if (i < NN) {
            g_rowptr[i] = excl;
            g_cur[i] = excl;
            g_dis[i] = rsqrtf(1.0f + (float)v);
        }
        __syncthreads();
        if (t == 0) carry_s += wsum[31];
        __syncthreads();
    }
    if (t == 0) g_rowptr[NN] = carry_s;
}

// ---------------- CSR fill ----------------
__global__ void k_fill(const void* __restrict__ ei) {
    int e = blockIdx.x * 256 + threadIdx.x;
    if (e >= EE) return;
    int r = edge_at(ei, e);
    int c = edge_at(ei, EE + e);
    if ((unsigned)r >= NN || (unsigned)c >= NN) return;
    int pos = atomicAdd(&g_cur[c], 1);
    if ((unsigned)pos < EE) {
        g_srcidx[pos] = r;
        g_ew[pos] = g_dis[r] * g_dis[c];
    }
}

// ---------------- fp32 -> bf16 hi/lo split of the input x (layer 1 only) ----------------
__global__ void __launch_bounds__(256) k_cvt_x(const float* __restrict__ src) {
    int idx = blockIdx.x * 256 + threadIdx.x;
    if (idx >= NN * FF / 4) return;
    float4 v = ((const float4*)src)[idx];
    __nv_bfloat16 h0 = __float2bfloat16(v.x), h1 = __float2bfloat16(v.y);
    __nv_bfloat16 h2 = __float2bfloat16(v.z), h3 = __float2bfloat16(v.w);
    __nv_bfloat16 l0 = __float2bfloat16(v.x - __bfloat162float(h0));
    __nv_bfloat16 l1 = __float2bfloat16(v.y - __bfloat162float(h1));
    __nv_bfloat16 l2 = __float2bfloat16(v.z - __bfloat162float(h2));
    __nv_bfloat16 l3 = __float2bfloat16(v.w - __bfloat162float(h3));
    __nv_bfloat162* ph = (__nv_bfloat162*)(g_Xhi + (size_t)idx * 4);
    __nv_bfloat162* pl = (__nv_bfloat162*)(g_Xlo + (size_t)idx * 4);
    ph[0] = __nv_bfloat162(h0, h1); ph[1] = __nv_bfloat162(h2, h3);
    pl[0] = __nv_bfloat162(l0, l1); pl[1] = __nv_bfloat162(l2, l3);
}

// ---------------- weight transpose + hi/lo split: Wt[n][k] = W[k][n] ----------------
__global__ void __launch_bounds__(256) k_cvt_w(const float* __restrict__ W) {
    __shared__ float tile[32][33];
    int tx = threadIdx.x & 31, ty = threadIdx.x >> 5;
    int bn = blockIdx.x * 32, bk = blockIdx.y * 32;
    for (int r = ty; r < 32; r += 8)
        tile[r][tx] = W[(size_t)(bk + r) * FF + bn + tx];
    __syncthreads();
    for (int r = ty; r < 32; r += 8) {
        float v = tile[tx][r];
        __nv_bfloat16 h = __float2bfloat16(v);
        g_Wthi[(size_t)(bn + r) * FF + bk + tx] = h;
        g_Wtlo[(size_t)(bn + r) * FF + bk + tx] = __float2bfloat16(v - __bfloat162float(h));
    }
}

// ---------------- fused split-bf16 GEMM: g_B = Xhi*Whi + Xhi*Wlo + Xlo*Whi ----------------
// BM=BN=128, 256 threads, 3-stage cp.async pipeline.
__global__ void __launch_bounds__(256) k_gemm_mma() {
    // [stage][tile: 0=Xhi 1=Xlo 2=Whi 3=Wlo][2048 bf16]
    __shared__ __align__(16) __nv_bfloat16 sm[NSTG][4][2048];

    const int tid = threadIdx.x;
    const int lane = tid & 31, wid = tid >> 5;
    const int n0 = blockIdx.x * BN, m0 = blockIdx.y * BM;
    const int mbase = (wid >> 2) * 64, nbase = (wid & 3) * 32;
    const uint32_t smb = stu32(sm);

    float d[4][4][4];
#pragma unroll
    for (int i = 0; i < 4; i++)
#pragma unroll
        for (int j = 0; j < 4; j++)
#pragma unroll
            for (int q = 0; q < 4; q++) d[i][j][q] = 0.0f;

    const int lrow = tid >> 1, lch = tid & 1;  // loader mapping
    auto load_tiles = [&](int it, int stg) {
        const int kb = it * BK;
        uint32_t dst = smb + stg * (4 * TILE_B) + tswz(lrow, lch);
        const size_t xoff = (size_t)(m0 + lrow) * FF + kb + lch * 8;
        const size_t woff = (size_t)(n0 + lrow) * FF + kb + lch * 8;
        int szx = (m0 + lrow) < NN ? 16 : 0;
        asm volatile("cp.async.cg.shared.global [%0], [%1], 16, %2;"
                     :: "r"(dst + 0 * TILE_B), "l"((const void*)(g_Xhi + xoff)), "r"(szx));
        asm volatile("cp.async.cg.shared.global [%0], [%1], 16, %2;"
                     :: "r"(dst + 1 * TILE_B), "l"((const void*)(g_Xlo + xoff)), "r"(szx));
        asm volatile("cp.async.cg.shared.global [%0], [%1], 16;"
                     :: "r"(dst + 2 * TILE_B), "l"((const void*)(g_Wthi + woff)));
        asm volatile("cp.async.cg.shared.global [%0], [%1], 16;"
                     :: "r"(dst + 3 * TILE_B), "l"((const void*)(g_Wtlo + woff)));
        asm volatile("cp.async.commit_group;" ::: "memory");
    };

    load_tiles(0, 0);
    load_tiles(1, 1);

    const int frow = lane & 15, fch = lane >> 4;   // fragment lane mapping
    for (int it = 0; it < NT; it++) {
        const int stg = it % NSTG;
        if (it + 2 < NT) {
            load_tiles(it + 2, (it + 2) % NSTG);
            asm volatile("cp.async.wait_group 2;" ::: "memory");
        } else if (it + 1 < NT) {
            asm volatile("cp.async.wait_group 1;" ::: "memory");
        } else {
            asm volatile("cp.async.wait_group 0;" ::: "memory");
        }
        __syncthreads();

        const uint32_t base = smb + stg * (4 * TILE_B);
        uint32_t aHi[4][4], aLo[4][4], bHi[4][2], bLo[4][2];
#pragma unroll
        for (int mf = 0; mf < 4; mf++) {
            uint32_t off = tswz(mbase + mf * 16 + frow, fch);
            asm volatile("ldmatrix.sync.aligned.m8n8.x4.shared.b16 {%0,%1,%2,%3}, [%4];"
                         : "=r"(aHi[mf][0]), "=r"(aHi[mf][1]), "=r"(aHi[mf][2]), "=r"(aHi[mf][3])
                         : "r"(base + 0 * TILE_B + off));
            asm volatile("ldmatrix.sync.aligned.m8n8.x4.shared.b16 {%0,%1,%2,%3}, [%4];"
                         : "=r"(aLo[mf][0]), "=r"(aLo[mf][1]), "=r"(aLo[mf][2]), "=r"(aLo[mf][3])
                         : "r"(base + 1 * TILE_B + off));
        }
#pragma unroll
        for (int nb = 0; nb < 2; nb++) {
            uint32_t off = tswz(nbase + nb * 16 + frow, fch);
            uint32_t r0, r1, r2, r3;
            asm volatile("ldmatrix.sync.aligned.m8n8.x4.shared.b16 {%0,%1,%2,%3}, [%4];"
                         : "=r"(r0), "=r"(r1), "=r"(r2), "=r"(r3)
                         : "r"(base + 2 * TILE_B + off));
            bHi[nb * 2][0] = r0; bHi[nb * 2][1] = r2;
            bHi[nb * 2 + 1][0] = r1; bHi[nb * 2 + 1][1] = r3;
            asm volatile("ldmatrix.sync.aligned.m8n8.x4.shared.b16 {%0,%1,%2,%3}, [%4];"
                         : "=r"(r0), "=r"(r1), "=r"(r2), "=r"(r3)
                         : "r"(base + 3 * TILE_B + off));
            bLo[nb * 2][0] = r0; bLo[nb * 2][1] = r2;
            bLo[nb * 2 + 1][0] = r1; bLo[nb * 2 + 1][1] = r3;
        }

#define MMA(A, B, mf, nf)                                                         \
        asm volatile(                                                             \
            "mma.sync.aligned.m16n8k16.row.col.f32.bf16.bf16.f32 "                \
            "{%0,%1,%2,%3}, {%4,%5,%6,%7}, {%8,%9}, {%0,%1,%2,%3};"               \
            : "+f"(d[mf][nf][0]), "+f"(d[mf][nf][1]),                             \
              "+f"(d[mf][nf][2]), "+f"(d[mf][nf][3])                              \
            : "r"(A[mf][0]), "r"(A[mf][1]), "r"(A[mf][2]), "r"(A[mf][3]),         \
              "r"(B[nf][0]), "r"(B[nf][1]))
#pragma unroll
        for (int mf = 0; mf < 4; mf++)
#pragma unroll
            for (int nf = 0; nf < 4; nf++) {
                MMA(aHi, bHi, mf, nf);
                MMA(aHi, bLo, mf, nf);
                MMA(aLo, bHi, mf, nf);
            }
#undef MMA
        __syncthreads();
    }

    // epilogue: write fp32 result to g_B
    const int g = lane >> 2, tg = lane & 3;
#pragma unroll
    for (int mf = 0; mf < 4; mf++) {
        int row0 = m0 + mbase + mf * 16 + g;
        int row1 = row0 + 8;
#pragma unroll
        for (int nf = 0; nf < 4; nf++) {
            int col = n0 + nbase + nf * 8 + tg * 2;
            if (row0 < NN)
                *(float2*)(g_B + (size_t)row0 * FF + col) = make_float2(d[mf][nf][0], d[mf][nf][1]);
            if (row1 < NN)
                *(float2*)(g_B + (size_t)row1 * FF + col) = make_float2(d[mf][nf][2], d[mf][nf][3]);
        }
    }
}

// ---------------- fused aggregation (reads g_B; writes hi/lo or fp32) ----------------
__global__ void __launch_bounds__(128) k_agg(const float* __restrict__ bias,
                                             int mode, float* __restrict__ extOut) {
    const float* h = g_B;
    __shared__ int   sh_src[128];
    __shared__ float sh_w[128];
    const int i = blockIdx.x;
    const int t = threadIdx.x;

    float dd = g_dis[i];
    float w0 = dd * dd;
    float4 acc = ((const float4*)(h + (size_t)i * FF))[t];
    acc.x *= w0; acc.y *= w0; acc.z *= w0; acc.w *= w0;

    const int s = g_rowptr[i], e2 = g_rowptr[i + 1];
    for (int base = s; base < e2; base += 128) {
        int m = e2 - base;
        if (m > 128) m = 128;
        if (t < m) {
            sh_src[t] = g_srcidx[base + t];
            sh_w[t]   = g_ew[base + t];
        }
        __syncthreads();
#pragma unroll 4
        for (int j = 0; j < m; j++) {
            const float4 v = ((const float4*)(h + (size_t)sh_src[j] * FF))[t];
            const float w = sh_w[j];
            acc.x += v.x * w; acc.y += v.y * w;
            acc.z += v.z * w; acc.w += v.w * w;
        }
        __syncthreads();
    }

    float4 bb = ((const float4*)bias)[t];
    acc.x += bb.x; acc.y += bb.y; acc.z += bb.z; acc.w += bb.w;

    if (mode) {
        acc.x = fmaxf(acc.x, 0.f); acc.y = fmaxf(acc.y, 0.f);
        acc.z = fmaxf(acc.z, 0.f); acc.w = fmaxf(acc.w, 0.f);
        __nv_bfloat16 h0 = __float2bfloat16(acc.x), h1 = __float2bfloat16(acc.y);
        __nv_bfloat16 h2 = __float2bfloat16(acc.z), h3 = __float2bfloat16(acc.w);
        __nv_bfloat16 l0 = __float2bfloat16(acc.x - __bfloat162float(h0));
        __nv_bfloat16 l1 = __float2bfloat16(acc.y - __bfloat162float(h1));
        __nv_bfloat16 l2 = __float2bfloat16(acc.z - __bfloat162float(h2));
        __nv_bfloat16 l3 = __float2bfloat16(acc.w - __bfloat162float(h3));
        size_t o = (size_t)i * FF + t * 4;
        __nv_bfloat162* ph = (__nv_bfloat162*)(g_Xhi + o);
        __nv_bfloat162* pl = (__nv_bfloat162*)(g_Xlo + o);
        ph[0] = __nv_bfloat162(h0, h1); ph[1] = __nv_bfloat162(h2, h3);
        pl[0] = __nv_bfloat162(l0, l1); pl[1] = __nv_bfloat162(l2, l3);
    } else {
        ((float4*)(extOut + (size_t)i * FF))[t] = acc;
    }
}

// ---------------- launcher (kernel launches ONLY) ----------------
extern "C" void kernel_launch(void* const* d_in, const int* in_sizes, int n_in,
                              void* d_out, int out_size) {
    const float* x   = (const float*)d_in[0];
    const void*  ei  = d_in[1];
    const float* W1  = (const float*)d_in[2];
    const float* b1  = (const float*)d_in[3];
    const float* W2  = (const float*)d_in[4];
    const float* b2  = (const float*)d_in[5];
    const float* W3  = (const float*)d_in[6];
    const float* b3  = (const float*)d_in[7];
    float* out       = (float*)d_out;

    dim3 gemm_grid(FF / BN, (NN + BM - 1) / BM);   // (4, 79)
    dim3 cvtw_grid(16, 16);
    int cvtx_blocks = (NN * FF / 4 + 255) / 256;

    // setup: detect dtype + zero deg (fused) -> degree -> scan+dis -> fill
    k_detect<<<41, 256>>>((const int*)ei);
    k_deg_acc<<<(EE + 255) / 256, 256>>>(ei);
    k_scan<<<1, 1024>>>();
    k_fill<<<(EE + 255) / 256, 256>>>(ei);

    // Layer 1
    k_cvt_w<<<cvtw_grid, 256>>>(W1);
    k_cvt_x<<<cvtx_blocks, 256>>>(x);
    k_gemm_mma<<<gemm_grid, 256>>>();
    k_agg<<<NN, 128>>>(b1, 1, nullptr);
    // Layer 2
    k_cvt_w<<<cvtw_grid, 256>>>(W2);
    k_gemm_mma<<<gemm_grid, 256>>>();
    k_agg<<<NN, 128>>>(b2, 1, nullptr);
    // Layer 3 (final, fp32 out, no relu)
    k_cvt_w<<<cvtw_grid, 256>>>(W3);
    k_gemm_mma<<<gemm_grid, 256>>>();
    k_agg<<<NN, 128>>>(b3, 0, out);
}